// round 1
// baseline (speedup 1.0000x reference)
#include <cuda_runtime.h>
#include <math.h>
#include <float.h>

// RepulsionLoss: B=8, N=4096, KNN=4, H=0.03
// loss = sum over all points of -d_k * exp(-d_k / H^2) for the 4 nearest
// neighbors (excluding self) of each point, d = squared euclidean distance.

#define B_SZ     8
#define N_SZ     4096
#define TILE     2048
#define THREADS  256
#define QCHUNKS  (N_SZ / THREADS)     // 16 query-chunks per batch
#define GRID_SZ  (B_SZ * QCHUNKS)     // 128 blocks
#define H2       (0.03f * 0.03f)

__device__ float g_partial[GRID_SZ];

__global__ __launch_bounds__(THREADS)
void repulsion_knn_kernel(const float* __restrict__ pc) {
    __shared__ float4 spts[TILE];            // 32 KB: candidate tile, padded xyz_
    __shared__ float  wsum[THREADS / 32];

    const int tid   = threadIdx.x;
    const int b     = blockIdx.x >> 4;       // / QCHUNKS
    const int qbase = (blockIdx.x & 15) * THREADS;
    const int q     = qbase + tid;

    const float* __restrict__ batch = pc + (size_t)b * N_SZ * 3;

    const float qx = batch[q * 3 + 0];
    const float qy = batch[q * 3 + 1];
    const float qz = batch[q * 3 + 2];

    // 5 smallest squared distances, ascending. Slot 0 will end up as the
    // self-distance (0); slots 1..4 are the KNN distances (matches the
    // reference's top_k(KNN+1) then drop-first).
    float d0 = FLT_MAX, d1 = FLT_MAX, d2 = FLT_MAX, d3 = FLT_MAX, d4 = FLT_MAX;

    for (int t = 0; t < N_SZ; t += TILE) {
        // Stage TILE candidate points into smem as padded float4.
        const float* __restrict__ src = batch + (size_t)t * 3;
        for (int e = tid; e < TILE * 3; e += THREADS) {
            int j = e / 3;
            int c = e - j * 3;
            reinterpret_cast<float*>(&spts[j])[c] = src[e];
        }
        __syncthreads();

        #pragma unroll 4
        for (int j = 0; j < TILE; ++j) {
            float4 p = spts[j];              // broadcast LDS.128
            float dx = p.x - qx;
            float dy = p.y - qy;
            float dz = p.z - qz;
            float d  = fmaf(dx, dx, fmaf(dy, dy, dz * dz));
            if (d < d4) {
                d4 = d;
                if (d4 < d3) { float tm = d3; d3 = d4; d4 = tm;
                  if (d3 < d2) { tm = d2; d2 = d3; d3 = tm;
                    if (d2 < d1) { tm = d1; d1 = d2; d2 = tm;
                      if (d1 < d0) { tm = d0; d0 = d1; d1 = tm; } } } }
            }
        }
        __syncthreads();
    }

    const float inv = -1.0f / H2;
    float loss = -d1 * expf(d1 * inv)
               - d2 * expf(d2 * inv)
               - d3 * expf(d3 * inv)
               - d4 * expf(d4 * inv);

    // Deterministic in-block reduction.
    #pragma unroll
    for (int o = 16; o > 0; o >>= 1)
        loss += __shfl_down_sync(0xffffffffu, loss, o);
    if ((tid & 31) == 0) wsum[tid >> 5] = loss;
    __syncthreads();
    if (tid == 0) {
        float s = 0.0f;
        #pragma unroll
        for (int w = 0; w < THREADS / 32; ++w) s += wsum[w];
        g_partial[blockIdx.x] = s;
    }
}

__global__ void repulsion_final_reduce(float* __restrict__ out) {
    __shared__ float ws[GRID_SZ / 32];
    const int tid = threadIdx.x;              // 128 threads
    float v = g_partial[tid];
    #pragma unroll
    for (int o = 16; o > 0; o >>= 1)
        v += __shfl_down_sync(0xffffffffu, v, o);
    if ((tid & 31) == 0) ws[tid >> 5] = v;
    __syncthreads();
    if (tid == 0) {
        float s = 0.0f;
        #pragma unroll
        for (int w = 0; w < GRID_SZ / 32; ++w) s += ws[w];
        out[0] = s;
    }
}

extern "C" void kernel_launch(void* const* d_in, const int* in_sizes, int n_in,
                              void* d_out, int out_size) {
    const float* pc = (const float*)d_in[0];
    repulsion_knn_kernel<<<GRID_SZ, THREADS>>>(pc);
    repulsion_final_reduce<<<1, 128>>>((float*)d_out);
}

// round 2
// speedup vs baseline: 2.1398x; 2.1398x over previous
#include <cuda_runtime.h>
#include <math.h>
#include <float.h>

// RepulsionLoss: B=8, N=4096, KNN=4, H=0.03
// loss = sum over points of -d_k * exp(-d_k/H^2) for the 4 nearest neighbors
// (excluding self). Strategy: branch-free top-5 selection (self lands in slot 0),
// GEMM-form distance v = |p|^2 - 2 p.q with per-query |q|^2 deferred to the end.

#define B_SZ     8
#define N_SZ     4096
#define THREADS  256
#define QPB      64                    // queries per block
#define SPLIT    4                     // candidate splits per query
#define TILE     2048                  // candidates staged in smem per pass
#define SEG      (TILE / SPLIT)        // 512 candidates per thread per tile
#define QCHUNKS  (N_SZ / QPB)          // 64
#define GRID_SZ  (B_SZ * QCHUNKS)      // 512 blocks
#define H2       (0.03f * 0.03f)

__device__ float g_partial[GRID_SZ];

// Branch-free insert of v into sorted 5-list (ascending), dropping the max.
__device__ __forceinline__ void ins5(float& d0, float& d1, float& d2,
                                     float& d3, float& d4, float v) {
    float t;
    d4 = fminf(d4, v);
    t = fminf(d3, d4); d4 = fmaxf(d3, d4); d3 = t;
    t = fminf(d2, d3); d3 = fmaxf(d2, d3); d2 = t;
    t = fminf(d1, d2); d2 = fmaxf(d1, d2); d1 = t;
    t = fminf(d0, d1); d1 = fmaxf(d0, d1); d0 = t;
}

__global__ __launch_bounds__(THREADS)
void repulsion_knn_kernel(const float* __restrict__ pc) {
    __shared__ float4 spts[TILE];            // 32 KB: (x, y, z, |p|^2)
    __shared__ float  mbuf[THREADS][5];      // 5 KB: partial top-5 lists
    __shared__ float  wsum[THREADS / 32];

    const int tid   = threadIdx.x;
    const int b     = blockIdx.x >> 6;               // / QCHUNKS
    const int qbase = (blockIdx.x & (QCHUNKS - 1)) * QPB;
    const int ql    = tid & (QPB - 1);
    const int split = tid >> 6;                      // warp-uniform
    const int q     = qbase + ql;

    const float* __restrict__ batch = pc + (size_t)b * N_SZ * 3;

    const float qx = batch[q * 3 + 0];
    const float qy = batch[q * 3 + 1];
    const float qz = batch[q * 3 + 2];
    const float m2x = -2.0f * qx, m2y = -2.0f * qy, m2z = -2.0f * qz;
    const float qsq = fmaf(qx, qx, fmaf(qy, qy, qz * qz));

    // Top-5 of shifted distances v = d - |q|^2, ascending. Self (v = -|q|^2)
    // generically ends in slot 0 and is dropped (matches ref's drop-first).
    float d0 = FLT_MAX, d1 = FLT_MAX, d2 = FLT_MAX, d3 = FLT_MAX, d4 = FLT_MAX;

    for (int t0 = 0; t0 < N_SZ; t0 += TILE) {
        // Stage xyz (coalesced global reads).
        const float* __restrict__ src = batch + (size_t)t0 * 3;
        for (int e = tid; e < TILE * 3; e += THREADS) {
            int j = e / 3;
            int c = e - j * 3;
            reinterpret_cast<float*>(&spts[j])[c] = src[e];
        }
        __syncthreads();
        // Fill w = |p|^2.
        for (int j = tid; j < TILE; j += THREADS) {
            float4 p = spts[j];
            spts[j].w = fmaf(p.x, p.x, fmaf(p.y, p.y, p.z * p.z));
        }
        __syncthreads();

        // Each thread scans its 512-candidate segment; all lanes of a warp
        // share the segment -> LDS.128 is a pure broadcast (no conflicts).
        const float4* __restrict__ seg = spts + split * SEG;
        #pragma unroll 8
        for (int i = 0; i < SEG; ++i) {
            float4 p = seg[i];
            float v = fmaf(p.x, m2x, p.w);
            v = fmaf(p.y, m2y, v);
            v = fmaf(p.z, m2z, v);
            ins5(d0, d1, d2, d3, d4, v);
        }
        __syncthreads();
    }

    // Publish partial lists and merge the 4 splits of each query.
    mbuf[tid][0] = d0; mbuf[tid][1] = d1; mbuf[tid][2] = d2;
    mbuf[tid][3] = d3; mbuf[tid][4] = d4;
    __syncthreads();

    float loss = 0.0f;
    if (split == 0) {
        #pragma unroll
        for (int s = 1; s < SPLIT; ++s) {
            const float* o = mbuf[ql + s * QPB];
            #pragma unroll
            for (int k = 0; k < 5; ++k) ins5(d0, d1, d2, d3, d4, o[k]);
        }
        // Undo the -|q|^2 shift, clamp like the reference, drop slot 0 (self).
        const float inv = -1.0f / H2;
        float s1 = fmaxf(d1 + qsq, 0.0f);
        float s2 = fmaxf(d2 + qsq, 0.0f);
        float s3 = fmaxf(d3 + qsq, 0.0f);
        float s4 = fmaxf(d4 + qsq, 0.0f);
        loss = -s1 * expf(s1 * inv)
             - s2 * expf(s2 * inv)
             - s3 * expf(s3 * inv)
             - s4 * expf(s4 * inv);
    }

    // Deterministic in-block reduction.
    #pragma unroll
    for (int o = 16; o > 0; o >>= 1)
        loss += __shfl_down_sync(0xffffffffu, loss, o);
    if ((tid & 31) == 0) wsum[tid >> 5] = loss;
    __syncthreads();
    if (tid == 0) {
        float s = 0.0f;
        #pragma unroll
        for (int w = 0; w < THREADS / 32; ++w) s += wsum[w];
        g_partial[blockIdx.x] = s;
    }
}

__global__ void repulsion_final_reduce(float* __restrict__ out) {
    __shared__ float ws[GRID_SZ / 32 > 0 ? GRID_SZ / 32 : 1];
    const int tid = threadIdx.x;              // 512 threads
    float v = g_partial[tid];
    #pragma unroll
    for (int o = 16; o > 0; o >>= 1)
        v += __shfl_down_sync(0xffffffffu, v, o);
    if ((tid & 31) == 0) ws[tid >> 5] = v;
    __syncthreads();
    if (tid == 0) {
        float s = 0.0f;
        #pragma unroll
        for (int w = 0; w < GRID_SZ / 32; ++w) s += ws[w];
        out[0] = s;
    }
}

extern "C" void kernel_launch(void* const* d_in, const int* in_sizes, int n_in,
                              void* d_out, int out_size) {
    const float* pc = (const float*)d_in[0];
    repulsion_knn_kernel<<<GRID_SZ, THREADS>>>(pc);
    repulsion_final_reduce<<<1, GRID_SZ>>>((float*)d_out);
}